// round 5
// baseline (speedup 1.0000x reference)
#include <cuda_runtime.h>
#include <cuda_bf16.h>
#include <cstdint>
#include <cstddef>

// Problem constants
#define D_MODEL 2048
#define N_HEADS 16
#define D_HEAD  128
#define WINDOW  512
#define BATCH   2
#define SEQ     4096
#define NB      (SEQ / WINDOW)
#define ROWS    (BATCH * SEQ)         // 8192
#define QKV_N   (3 * D_MODEL)         // 6144
#define KDIM    D_MODEL               // 2048
#define SCALE_F 0.08838834764831845f
#define LOG2E_F 1.4426950408889634f

// ---------------------------------------------------------------------------
// Scratch (__device__ globals; no allocation allowed)
// ---------------------------------------------------------------------------
__device__ float          g_qkv[(size_t)ROWS * QKV_N];
__device__ __nv_bfloat16  g_ahi[(size_t)ROWS * KDIM];
__device__ __nv_bfloat16  g_alo[(size_t)ROWS * KDIM];
__device__ __nv_bfloat16  g_wqkv_hi[(size_t)QKV_N * KDIM];
__device__ __nv_bfloat16  g_wqkv_lo[(size_t)QKV_N * KDIM];
__device__ __nv_bfloat16  g_wout_hi[(size_t)D_MODEL * KDIM];
__device__ __nv_bfloat16  g_wout_lo[(size_t)D_MODEL * KDIM];

// ---------------------------------------------------------------------------
// Baseline-ISA helpers (NO tcgen05 — ptxas target is compute_103)
// ---------------------------------------------------------------------------
__device__ __forceinline__ uint32_t smem_u32(const void* p) {
    uint32_t a;
    asm("{ .reg .u64 t; cvta.to.shared.u64 t, %1; cvt.u32.u64 %0, t; }" : "=r"(a) : "l"(p));
    return a;
}
#define CP_ASYNC16(dst, src) \
    asm volatile("cp.async.cg.shared.global [%0], [%1], 16;" :: "r"(dst), "l"(src))
#define CP_COMMIT()   asm volatile("cp.async.commit_group;" ::: "memory")
#define CP_WAITG(n)   asm volatile("cp.async.wait_group %0;" :: "n"(n) : "memory")

__device__ __forceinline__ void ldmx4(uint32_t* r, uint32_t addr) {
    asm volatile("ldmatrix.sync.aligned.m8n8.x4.shared.b16 {%0,%1,%2,%3}, [%4];"
                 : "=r"(r[0]), "=r"(r[1]), "=r"(r[2]), "=r"(r[3]) : "r"(addr));
}
__device__ __forceinline__ void ldmx4t(uint32_t* r, uint32_t addr) {
    asm volatile("ldmatrix.sync.aligned.m8n8.x4.trans.shared.b16 {%0,%1,%2,%3}, [%4];"
                 : "=r"(r[0]), "=r"(r[1]), "=r"(r[2]), "=r"(r[3]) : "r"(addr));
}
__device__ __forceinline__ void mma_bf16(float* d, const uint32_t* a, const uint32_t* b) {
    asm volatile("mma.sync.aligned.m16n8k16.row.col.f32.bf16.bf16.f32 "
                 "{%0,%1,%2,%3}, {%4,%5,%6,%7}, {%8,%9}, {%0,%1,%2,%3};"
                 : "+f"(d[0]), "+f"(d[1]), "+f"(d[2]), "+f"(d[3])
                 : "r"(a[0]), "r"(a[1]), "r"(a[2]), "r"(a[3]), "r"(b[0]), "r"(b[1]));
}
__device__ __forceinline__ void split2(float a, float b, uint32_t& h, uint32_t& l) {
    __nv_bfloat16 ha = __float2bfloat16(a), hb = __float2bfloat16(b);
    __nv_bfloat162 hv(ha, hb);
    __nv_bfloat162 lv(__float2bfloat16(a - __bfloat162float(ha)),
                      __float2bfloat16(b - __bfloat162float(hb)));
    h = *(uint32_t*)&hv; l = *(uint32_t*)&lv;
}

// ---------------------------------------------------------------------------
// Conversion kernels
// ---------------------------------------------------------------------------
__global__ void split_hilo(const float* __restrict__ in, __nv_bfloat16* __restrict__ hi,
                           __nv_bfloat16* __restrict__ lo, int n4)
{
    int i = blockIdx.x * blockDim.x + threadIdx.x;
    if (i >= n4) return;
    float4 v = ((const float4*)in)[i];
    uint32_t h0, l0, h1, l1;
    split2(v.x, v.y, h0, l0);
    split2(v.z, v.w, h1, l1);
    ((uint32_t*)hi)[i * 2]     = h0;
    ((uint32_t*)hi)[i * 2 + 1] = h1;
    ((uint32_t*)lo)[i * 2]     = l0;
    ((uint32_t*)lo)[i * 2 + 1] = l1;
}

// W[K,N] fp32 -> Wt hi/lo [N,K] bf16 (transpose + split)
__global__ void transpose_split(const float* __restrict__ W, __nv_bfloat16* __restrict__ hi,
                                __nv_bfloat16* __restrict__ lo, int K, int N)
{
    __shared__ float t[32][33];
    const int n0 = blockIdx.x * 32, k0 = blockIdx.y * 32;
    const int tx = threadIdx.x, ty = threadIdx.y;
    #pragma unroll
    for (int i = 0; i < 4; i++)
        t[ty + i * 8][tx] = W[(size_t)(k0 + ty + i * 8) * N + n0 + tx];
    __syncthreads();
    #pragma unroll
    for (int i = 0; i < 4; i++) {
        float v = t[tx][ty + i * 8];
        size_t o = (size_t)(n0 + ty + i * 8) * K + k0 + tx;
        __nv_bfloat16 h = __float2bfloat16(v);
        hi[o] = h;
        lo[o] = __float2bfloat16(v - __bfloat162float(h));
    }
}

// ---------------------------------------------------------------------------
// mma.sync split-bf16 GEMM, 4-stage cp.async pipeline, 512 threads.
//   C[M,N] = A @ Wt^T + bias.  CTA 128x128, 16 warps (32x32 each), BK=32.
//   32 accums/thread -> ~90 regs -> 16 warps resident (4/SMSP).
// ---------------------------------------------------------------------------
#define GBM 128
#define GBN 128
#define GBK 32
#define LDT 40
#define BUF_B (128 * LDT * 2)         // 10240 B
#define STAGE_B (4 * BUF_B)           // 40960 B
#define NSTAGE 4
#define GEMM_SMEM (NSTAGE * STAGE_B)  // 163840 B

__device__ __forceinline__ void load_stage(
    uint32_t sb, uint32_t stage,
    const __nv_bfloat16* __restrict__ ahi, const __nv_bfloat16* __restrict__ alo,
    const __nv_bfloat16* __restrict__ bhi, const __nv_bfloat16* __restrict__ blo,
    int bm, int bn, int k0, int tid)
{
    #pragma unroll
    for (int it = 0; it < 4; it++) {
        const int c = tid + it * 512;
        const int buf = c >> 9;
        const int row = (c >> 2) & 127;
        const int kc = c & 3;
        const __nv_bfloat16* src;
        int grow;
        if (buf == 0)      { src = ahi; grow = bm + row; }
        else if (buf == 1) { src = alo; grow = bm + row; }
        else if (buf == 2) { src = bhi; grow = bn + row; }
        else               { src = blo; grow = bn + row; }
        const uint32_t dst = sb + stage + buf * BUF_B + row * (LDT * 2) + kc * 16;
        CP_ASYNC16(dst, src + (size_t)grow * KDIM + k0 + kc * 8);
    }
}

__global__ __launch_bounds__(512, 1)
void gemm_mma_kernel(const __nv_bfloat16* __restrict__ ahi, const __nv_bfloat16* __restrict__ alo,
                     const __nv_bfloat16* __restrict__ bhi, const __nv_bfloat16* __restrict__ blo,
                     const float* __restrict__ bias, float* __restrict__ C, int N)
{
    extern __shared__ char smem[];
    const uint32_t sb = smem_u32(smem);
    const int tid = threadIdx.x;
    const int wid = tid >> 5;
    const int lane = tid & 31;
    const int bm = blockIdx.y * GBM;
    const int bn = blockIdx.x * GBN;
    const int warp_m = (wid & 3) * 32;     // 4 warp-rows
    const int warp_n = (wid >> 2) * 32;    // 4 warp-cols

    float d[2][4][4];
    #pragma unroll
    for (int i = 0; i < 2; i++)
        #pragma unroll
        for (int j = 0; j < 4; j++)
            #pragma unroll
            for (int r = 0; r < 4; r++) d[i][j][r] = 0.0f;

    const int nk = KDIM / GBK;  // 64

    #pragma unroll
    for (int s = 0; s < NSTAGE; s++) {
        load_stage(sb, s * STAGE_B, ahi, alo, bhi, blo, bm, bn, s * GBK, tid);
        CP_COMMIT();
    }
    CP_WAITG(2);            // stages 0,1 landed
    __syncthreads();

    for (int kt = 0; kt < nk; kt++) {
        const uint32_t stage = (uint32_t)(kt % NSTAGE) * STAGE_B;

        #pragma unroll
        for (int k16 = 0; k16 < 2; k16++) {
            uint32_t ra[2][2][4];   // [hi/lo][mf]
            uint32_t rb[2][2][4];   // [hi/lo][nf2]
            #pragma unroll
            for (int hl = 0; hl < 2; hl++) {
                const uint32_t abase = sb + stage + hl * BUF_B;
                #pragma unroll
                for (int mf = 0; mf < 2; mf++) {
                    const int row = warp_m + mf * 16 + (lane & 15);
                    const int col = ((lane >> 4) << 3) + k16 * 16;
                    ldmx4(ra[hl][mf], abase + row * (LDT * 2) + col * 2);
                }
                const uint32_t bbase = sb + stage + (2 + hl) * BUF_B;
                #pragma unroll
                for (int nf2 = 0; nf2 < 2; nf2++) {
                    const int row = warp_n + nf2 * 16 + ((lane >> 4) << 3) + (lane & 7);
                    const int col = (((lane >> 3) & 1) << 3) + k16 * 16;
                    ldmx4(rb[hl][nf2], bbase + row * (LDT * 2) + col * 2);
                }
            }
            #pragma unroll
            for (int t = 0; t < 3; t++) {
                const int ah = (t == 2) ? 1 : 0;
                const int bh = (t == 1) ? 1 : 0;
                #pragma unroll
                for (int mf = 0; mf < 2; mf++)
                    #pragma unroll
                    for (int nf = 0; nf < 4; nf++)
                        mma_bf16(d[mf][nf], ra[ah][mf], &rb[bh][nf >> 1][(nf & 1) * 2]);
            }
        }

        __syncthreads();    // all warps done reading `stage`
        if (kt + NSTAGE < nk)
            load_stage(sb, stage, ahi, alo, bhi, blo, bm, bn, (kt + NSTAGE) * GBK, tid);
        CP_COMMIT();
        CP_WAITG(2);        // stage kt+1 (and kt+2) landed
        __syncthreads();
    }

    #pragma unroll
    for (int nf = 0; nf < 4; nf++) {
        const int c0 = bn + warp_n + nf * 8 + (lane & 3) * 2;
        const float b0 = bias[c0], b1 = bias[c0 + 1];
        #pragma unroll
        for (int mf = 0; mf < 2; mf++) {
            const int r0 = bm + warp_m + mf * 16 + (lane >> 2);
            float2 v0, v1;
            v0.x = d[mf][nf][0] + b0; v0.y = d[mf][nf][1] + b1;
            v1.x = d[mf][nf][2] + b0; v1.y = d[mf][nf][3] + b1;
            *(float2*)&C[(size_t)r0 * N + c0]       = v0;
            *(float2*)&C[(size_t)(r0 + 8) * N + c0] = v1;
        }
    }
}

// ---------------------------------------------------------------------------
// Tensor-core windowed causal flash attention (3-term split-bf16).
//   Unchanged from R4 (passing, rel_err 2.5e-5).
// ---------------------------------------------------------------------------
#define SQE 136
#define SQB (SQE * 2)
#define ATILE_B (64 * SQB)      // 17408 B
#define ATTN_SMEM (4 * ATILE_B) // 69632 B

__device__ __forceinline__ void load_conv(char* hi, char* lo, const float* __restrict__ src)
{
    const int tid = threadIdx.x;
    #pragma unroll
    for (int it = 0; it < 16; it++) {
        const int lin = tid + it * 128;
        const int r = lin >> 5;
        const int c = (lin & 31) * 4;
        float4 v = *(const float4*)&src[(size_t)r * QKV_N + c];
        uint32_t h0, l0, h1, l1;
        split2(v.x, v.y, h0, l0);
        split2(v.z, v.w, h1, l1);
        const int byte = r * SQB + c * 2;
        *(uint32_t*)(hi + byte)     = h0;
        *(uint32_t*)(hi + byte + 4) = h1;
        *(uint32_t*)(lo + byte)     = l0;
        *(uint32_t*)(lo + byte + 4) = l1;
    }
}

__global__ __launch_bounds__(128)
void attn_mma_kernel(const float* __restrict__ qkv,
                     __nv_bfloat16* __restrict__ ohi, __nv_bfloat16* __restrict__ olo)
{
    extern __shared__ char asmem[];
    char* QHI = asmem;
    char* QLO = asmem + ATILE_B;
    char* KVH = asmem + 2 * ATILE_B;
    char* KVL = asmem + 3 * ATILE_B;
    const uint32_t sb = smem_u32(asmem);
    const uint32_t KVH_U = sb + 2 * ATILE_B;
    const uint32_t KVL_U = sb + 3 * ATILE_B;

    const int tid = threadIdx.x;
    const int wid = tid >> 5;
    const int lane = tid & 31;
    const int qb = blockIdx.x;
    const int n  = blockIdx.y;
    const int bh = blockIdx.z;
    const int b  = bh >> 4;
    const int h  = bh & 15;

    const size_t row0 = (size_t)b * SEQ + (size_t)n * WINDOW;
    const float* qptr = qkv + (row0 + qb * 64) * QKV_N + h * D_HEAD;
    const float* kbase = qkv + row0 * QKV_N + h * D_HEAD + D_MODEL;
    const float* vbase = qkv + row0 * QKV_N + h * D_HEAD + 2 * D_MODEL;

    load_conv(QHI, QLO, qptr);

    const int warp_m = wid * 16;
    const int r0 = lane >> 2;
    const int qq = lane & 3;

    float o[16][4];
    #pragma unroll
    for (int j = 0; j < 16; j++)
        #pragma unroll
        for (int r = 0; r < 4; r++) o[j][r] = 0.0f;
    float m0 = -1e30f, m1 = -1e30f, l0 = 0.0f, l1 = 0.0f;

    for (int jt = 0; jt <= qb; jt++) {
        __syncthreads();
        load_conv(KVH, KVL, kbase + (size_t)(jt * 64) * QKV_N);
        __syncthreads();

        float s[8][4];
        #pragma unroll
        for (int j = 0; j < 8; j++)
            #pragma unroll
            for (int r = 0; r < 4; r++) s[j][r] = 0.0f;

        #pragma unroll
        for (int k16 = 0; k16 < 8; k16++) {
            uint32_t ra[2][4], rb[2][4][4];
            #pragma unroll
            for (int hl = 0; hl < 2; hl++) {
                const uint32_t ab = sb + (hl ? ATILE_B : 0u);
                ldmx4(ra[hl], ab + (warp_m + (lane & 15)) * SQB
                                 + (((lane >> 4) << 3) + k16 * 16) * 2);
                const uint32_t bb = hl ? KVL_U : KVH_U;
                #pragma unroll
                for (int g = 0; g < 4; g++) {
                    const int row = g * 16 + ((lane >> 4) << 3) + (lane & 7);
                    const int col = (((lane >> 3) & 1) << 3) + k16 * 16;
                    ldmx4(rb[hl][g], bb + row * SQB + col * 2);
                }
            }
            #pragma unroll
            for (int t = 0; t < 3; t++) {
                const int ah = (t == 2) ? 1 : 0;
                const int bl = (t == 1) ? 1 : 0;
                #pragma unroll
                for (int j = 0; j < 8; j++)
                    mma_bf16(s[j], ra[ah], &rb[bl][j >> 1][(j & 1) * 2]);
            }
        }

        const int rg0 = warp_m + r0;
        #pragma unroll
        for (int j = 0; j < 8; j++)
            #pragma unroll
            for (int r = 0; r < 4; r++) s[j][r] *= SCALE_F;
        if (jt == qb) {
            #pragma unroll
            for (int j = 0; j < 8; j++) {
                const int c0 = j * 8 + qq * 2;
                if (c0     > rg0)     s[j][0] = -1e30f;
                if (c0 + 1 > rg0)     s[j][1] = -1e30f;
                if (c0     > rg0 + 8) s[j][2] = -1e30f;
                if (c0 + 1 > rg0 + 8) s[j][3] = -1e30f;
            }
        }

        float mx0 = -1e30f, mx1 = -1e30f;
        #pragma unroll
        for (int j = 0; j < 8; j++) {
            mx0 = fmaxf(mx0, fmaxf(s[j][0], s[j][1]));
            mx1 = fmaxf(mx1, fmaxf(s[j][2], s[j][3]));
        }
        #pragma unroll
        for (int off = 1; off < 4; off <<= 1) {
            mx0 = fmaxf(mx0, __shfl_xor_sync(0xffffffffu, mx0, off));
            mx1 = fmaxf(mx1, __shfl_xor_sync(0xffffffffu, mx1, off));
        }
        const float mn0 = fmaxf(m0, mx0), mn1 = fmaxf(m1, mx1);
        const float f0 = exp2f((m0 - mn0) * LOG2E_F);
        const float f1 = exp2f((m1 - mn1) * LOG2E_F);
        float rs0 = 0.0f, rs1 = 0.0f;
        #pragma unroll
        for (int j = 0; j < 8; j++) {
            s[j][0] = exp2f((s[j][0] - mn0) * LOG2E_F); rs0 += s[j][0];
            s[j][1] = exp2f((s[j][1] - mn0) * LOG2E_F); rs0 += s[j][1];
            s[j][2] = exp2f((s[j][2] - mn1) * LOG2E_F); rs1 += s[j][2];
            s[j][3] = exp2f((s[j][3] - mn1) * LOG2E_F); rs1 += s[j][3];
        }
        #pragma unroll
        for (int off = 1; off < 4; off <<= 1) {
            rs0 += __shfl_xor_sync(0xffffffffu, rs0, off);
            rs1 += __shfl_xor_sync(0xffffffffu, rs1, off);
        }
        l0 = l0 * f0 + rs0; m0 = mn0;
        l1 = l1 * f1 + rs1; m1 = mn1;
        #pragma unroll
        for (int j = 0; j < 16; j++) {
            o[j][0] *= f0; o[j][1] *= f0;
            o[j][2] *= f1; o[j][3] *= f1;
        }

        uint32_t pah[4][4], pal[4][4];
        #pragma unroll
        for (int kc = 0; kc < 4; kc++) {
            split2(s[2 * kc][0],     s[2 * kc][1],     pah[kc][0], pal[kc][0]);
            split2(s[2 * kc][2],     s[2 * kc][3],     pah[kc][1], pal[kc][1]);
            split2(s[2 * kc + 1][0], s[2 * kc + 1][1], pah[kc][2], pal[kc][2]);
            split2(s[2 * kc + 1][2], s[2 * kc + 1][3], pah[kc][3], pal[kc][3]);
        }

        __syncthreads();
        load_conv(KVH, KVL, vbase + (size_t)(jt * 64) * QKV_N);
        __syncthreads();

        const int vrow_part = ((lane >> 3) & 1) * 8 + (lane & 7);
        const int vcol_part = (lane >> 4) * 8;
        #pragma unroll
        for (int kc = 0; kc < 4; kc++) {
            #pragma unroll
            for (int d16 = 0; d16 < 8; d16++) {
                uint32_t vh[4], vl[4];
                const uint32_t off = (kc * 16 + vrow_part) * SQB + (d16 * 16 + vcol_part) * 2;
                ldmx4t(vh, KVH_U + off);
                ldmx4t(vl, KVL_U + off);
                mma_bf16(o[2 * d16],     pah[kc], &vh[0]);
                mma_bf16(o[2 * d16 + 1], pah[kc], &vh[2]);
                mma_bf16(o[2 * d16],     pah[kc], &vl[0]);
                mma_bf16(o[2 * d16 + 1], pah[kc], &vl[2]);
                mma_bf16(o[2 * d16],     pal[kc], &vh[0]);
                mma_bf16(o[2 * d16 + 1], pal[kc], &vh[2]);
            }
        }
    }

    const float inv0 = 1.0f / l0, inv1 = 1.0f / l1;
    const size_t gr0 = row0 + qb * 64 + warp_m + r0;
    const size_t gr1 = gr0 + 8;
    #pragma unroll
    for (int j = 0; j < 16; j++) {
        const int col = h * D_HEAD + j * 8 + qq * 2;
        uint32_t h0, lo0, h1, lo1;
        split2(o[j][0] * inv0, o[j][1] * inv0, h0, lo0);
        split2(o[j][2] * inv1, o[j][3] * inv1, h1, lo1);
        *(uint32_t*)&ohi[gr0 * KDIM + col] = h0;
        *(uint32_t*)&olo[gr0 * KDIM + col] = lo0;
        *(uint32_t*)&ohi[gr1 * KDIM + col] = h1;
        *(uint32_t*)&olo[gr1 * KDIM + col] = lo1;
    }
}

// ---------------------------------------------------------------------------
extern "C" void kernel_launch(void* const* d_in, const int* in_sizes, int n_in,
                              void* d_out, int out_size)
{
    const float* x    = (const float*)d_in[0];
    const float* Wqkv = (const float*)d_in[1];
    const float* bqkv = (const float*)d_in[2];
    const float* Wout = (const float*)d_in[3];
    const float* bout = (const float*)d_in[4];
    float* out = (float*)d_out;

    float* qkv;
    __nv_bfloat16 *ahi, *alo, *wqh, *wql, *woh, *wol;
    cudaGetSymbolAddress((void**)&qkv, g_qkv);
    cudaGetSymbolAddress((void**)&ahi, g_ahi);
    cudaGetSymbolAddress((void**)&alo, g_alo);
    cudaGetSymbolAddress((void**)&wqh, g_wqkv_hi);
    cudaGetSymbolAddress((void**)&wql, g_wqkv_lo);
    cudaGetSymbolAddress((void**)&woh, g_wout_hi);
    cudaGetSymbolAddress((void**)&wol, g_wout_lo);

    cudaFuncSetAttribute(gemm_mma_kernel,
                         cudaFuncAttributeMaxDynamicSharedMemorySize, GEMM_SMEM);
    cudaFuncSetAttribute(attn_mma_kernel,
                         cudaFuncAttributeMaxDynamicSharedMemorySize, ATTN_SMEM);

    transpose_split<<<dim3(QKV_N / 32, KDIM / 32), dim3(32, 8)>>>(Wqkv, wqh, wql, KDIM, QKV_N);
    transpose_split<<<dim3(D_MODEL / 32, KDIM / 32), dim3(32, 8)>>>(Wout, woh, wol, KDIM, D_MODEL);

    {
        const int n4 = ROWS * D_MODEL / 4;
        split_hilo<<<(n4 + 255) / 256, 256>>>(x, ahi, alo, n4);
    }
    gemm_mma_kernel<<<dim3(QKV_N / GBN, ROWS / GBM), 512, GEMM_SMEM>>>(
        ahi, alo, wqh, wql, bqkv, qkv, QKV_N);

    attn_mma_kernel<<<dim3(WINDOW / 64, NB, BATCH * N_HEADS), 128, ATTN_SMEM>>>(qkv, ahi, alo);

    gemm_mma_kernel<<<dim3(D_MODEL / GBN, ROWS / GBM), 512, GEMM_SMEM>>>(
        ahi, alo, woh, wol, bout, out, D_MODEL);
}

// round 6
// speedup vs baseline: 1.1994x; 1.1994x over previous
#include <cuda_runtime.h>
#include <cuda_bf16.h>
#include <cstdint>
#include <cstddef>

// Problem constants
#define D_MODEL 2048
#define N_HEADS 16
#define D_HEAD  128
#define WINDOW  512
#define BATCH   2
#define SEQ     4096
#define NB      (SEQ / WINDOW)
#define ROWS    (BATCH * SEQ)         // 8192
#define QKV_N   (3 * D_MODEL)         // 6144
#define KDIM    D_MODEL               // 2048
#define SCALE_F 0.08838834764831845f
#define LOG2E_F 1.4426950408889634f

// ---------------------------------------------------------------------------
// Scratch (__device__ globals; no allocation allowed)
// ---------------------------------------------------------------------------
__device__ float          g_qkv[(size_t)ROWS * QKV_N];
__device__ __nv_bfloat16  g_ahi[(size_t)ROWS * KDIM];
__device__ __nv_bfloat16  g_alo[(size_t)ROWS * KDIM];
__device__ __nv_bfloat16  g_wqkv_hi[(size_t)QKV_N * KDIM];
__device__ __nv_bfloat16  g_wqkv_lo[(size_t)QKV_N * KDIM];
__device__ __nv_bfloat16  g_wout_hi[(size_t)D_MODEL * KDIM];
__device__ __nv_bfloat16  g_wout_lo[(size_t)D_MODEL * KDIM];

// ---------------------------------------------------------------------------
// Baseline-ISA helpers (NO tcgen05 — ptxas target is compute_103)
// ---------------------------------------------------------------------------
__device__ __forceinline__ uint32_t smem_u32(const void* p) {
    uint32_t a;
    asm("{ .reg .u64 t; cvta.to.shared.u64 t, %1; cvt.u32.u64 %0, t; }" : "=r"(a) : "l"(p));
    return a;
}
#define CP_ASYNC16(dst, src) \
    asm volatile("cp.async.cg.shared.global [%0], [%1], 16;" :: "r"(dst), "l"(src))
#define CP_COMMIT()   asm volatile("cp.async.commit_group;" ::: "memory")
#define CP_WAITG(n)   asm volatile("cp.async.wait_group %0;" :: "n"(n) : "memory")

__device__ __forceinline__ void ldmx4(uint32_t* r, uint32_t addr) {
    asm volatile("ldmatrix.sync.aligned.m8n8.x4.shared.b16 {%0,%1,%2,%3}, [%4];"
                 : "=r"(r[0]), "=r"(r[1]), "=r"(r[2]), "=r"(r[3]) : "r"(addr));
}
__device__ __forceinline__ void ldmx4t(uint32_t* r, uint32_t addr) {
    asm volatile("ldmatrix.sync.aligned.m8n8.x4.trans.shared.b16 {%0,%1,%2,%3}, [%4];"
                 : "=r"(r[0]), "=r"(r[1]), "=r"(r[2]), "=r"(r[3]) : "r"(addr));
}
__device__ __forceinline__ void mma_bf16(float* d, const uint32_t* a, const uint32_t* b) {
    asm volatile("mma.sync.aligned.m16n8k16.row.col.f32.bf16.bf16.f32 "
                 "{%0,%1,%2,%3}, {%4,%5,%6,%7}, {%8,%9}, {%0,%1,%2,%3};"
                 : "+f"(d[0]), "+f"(d[1]), "+f"(d[2]), "+f"(d[3])
                 : "r"(a[0]), "r"(a[1]), "r"(a[2]), "r"(a[3]), "r"(b[0]), "r"(b[1]));
}
__device__ __forceinline__ void split2(float a, float b, uint32_t& h, uint32_t& l) {
    __nv_bfloat16 ha = __float2bfloat16(a), hb = __float2bfloat16(b);
    __nv_bfloat162 hv(ha, hb);
    __nv_bfloat162 lv(__float2bfloat16(a - __bfloat162float(ha)),
                      __float2bfloat16(b - __bfloat162float(hb)));
    h = *(uint32_t*)&hv; l = *(uint32_t*)&lv;
}

// ---------------------------------------------------------------------------
// Conversion kernels
// ---------------------------------------------------------------------------
__global__ void split_hilo(const float* __restrict__ in, __nv_bfloat16* __restrict__ hi,
                           __nv_bfloat16* __restrict__ lo, int n4)
{
    int i = blockIdx.x * blockDim.x + threadIdx.x;
    if (i >= n4) return;
    float4 v = ((const float4*)in)[i];
    uint32_t h0, l0, h1, l1;
    split2(v.x, v.y, h0, l0);
    split2(v.z, v.w, h1, l1);
    ((uint32_t*)hi)[i * 2]     = h0;
    ((uint32_t*)hi)[i * 2 + 1] = h1;
    ((uint32_t*)lo)[i * 2]     = l0;
    ((uint32_t*)lo)[i * 2 + 1] = l1;
}

// W[K,N] fp32 -> Wt hi/lo [N,K] bf16 (transpose + split)
__global__ void transpose_split(const float* __restrict__ W, __nv_bfloat16* __restrict__ hi,
                                __nv_bfloat16* __restrict__ lo, int K, int N)
{
    __shared__ float t[32][33];
    const int n0 = blockIdx.x * 32, k0 = blockIdx.y * 32;
    const int tx = threadIdx.x, ty = threadIdx.y;
    #pragma unroll
    for (int i = 0; i < 4; i++)
        t[ty + i * 8][tx] = W[(size_t)(k0 + ty + i * 8) * N + n0 + tx];
    __syncthreads();
    #pragma unroll
    for (int i = 0; i < 4; i++) {
        float v = t[tx][ty + i * 8];
        size_t o = (size_t)(n0 + ty + i * 8) * K + k0 + tx;
        __nv_bfloat16 h = __float2bfloat16(v);
        hi[o] = h;
        lo[o] = __float2bfloat16(v - __bfloat162float(h));
    }
}

// ---------------------------------------------------------------------------
// mma.sync split-bf16 GEMM.  CTA 128x128, 8 warps (64x32 each), BK=64.
//   3-stage pipeline, ONE __syncthreads per k-iteration:
//     load(chunk kt+1 -> slot (kt+1)%3); commit; wait_group(1); bar; compute(kt)
//   WAR-safe: slot written at kt == slot read at kt-2 (3 stages, distance 2),
//   and every warp crossed the kt-1 barrier after finishing kt-2's reads.
// ---------------------------------------------------------------------------
#define GBM 128
#define GBN 128
#define GBK 64
#define LDT 72                        // padded row stride (bf16); 144 B
#define BUF_B (128 * LDT * 2)         // 18432 B
#define STAGE_B (4 * BUF_B)           // 73728 B
#define NSTAGE 3
#define GEMM_SMEM (NSTAGE * STAGE_B)  // 221184 B

__device__ __forceinline__ void load_stage(
    uint32_t sb, uint32_t stage,
    const __nv_bfloat16* __restrict__ ahi, const __nv_bfloat16* __restrict__ alo,
    const __nv_bfloat16* __restrict__ bhi, const __nv_bfloat16* __restrict__ blo,
    int bm, int bn, int k0, int tid)
{
    // 4 bufs x 128 rows x 8 chunks(16B) = 4096 cp.async; 16 per thread
    #pragma unroll
    for (int it = 0; it < 16; it++) {
        const int c = tid + it * 256;
        const int buf = c >> 10;
        const int row = (c >> 3) & 127;
        const int kc = c & 7;
        const __nv_bfloat16* src;
        int grow;
        if (buf == 0)      { src = ahi; grow = bm + row; }
        else if (buf == 1) { src = alo; grow = bm + row; }
        else if (buf == 2) { src = bhi; grow = bn + row; }
        else               { src = blo; grow = bn + row; }
        const uint32_t dst = sb + stage + buf * BUF_B + row * (LDT * 2) + kc * 16;
        CP_ASYNC16(dst, src + (size_t)grow * KDIM + k0 + kc * 8);
    }
}

__global__ __launch_bounds__(256, 1)
void gemm_mma_kernel(const __nv_bfloat16* __restrict__ ahi, const __nv_bfloat16* __restrict__ alo,
                     const __nv_bfloat16* __restrict__ bhi, const __nv_bfloat16* __restrict__ blo,
                     const float* __restrict__ bias, float* __restrict__ C, int N)
{
    extern __shared__ char smem[];
    const uint32_t sb = smem_u32(smem);
    const int tid = threadIdx.x;
    const int wid = tid >> 5;
    const int lane = tid & 31;
    const int bm = blockIdx.y * GBM;
    const int bn = blockIdx.x * GBN;
    const int warp_m = (wid >> 2) * 64;
    const int warp_n = (wid & 3) * 32;

    float d[4][4][4];
    #pragma unroll
    for (int i = 0; i < 4; i++)
        #pragma unroll
        for (int j = 0; j < 4; j++)
            #pragma unroll
            for (int r = 0; r < 4; r++) d[i][j][r] = 0.0f;

    const int nk = KDIM / GBK;  // 32

    // prologue: chunk 0 -> slot 0
    load_stage(sb, 0, ahi, alo, bhi, blo, bm, bn, 0, tid);
    CP_COMMIT();

    for (int kt = 0; kt < nk; kt++) {
        // issue chunk kt+1 into slot (kt+1)%3 (== slot read at kt-2)
        if (kt + 1 < nk)
            load_stage(sb, (uint32_t)((kt + 1) % NSTAGE) * STAGE_B,
                       ahi, alo, bhi, blo, bm, bn, (kt + 1) * GBK, tid);
        CP_COMMIT();            // unconditional: keeps FIFO group accounting exact
        CP_WAITG(1);            // all but newest group done => chunk kt landed
        __syncthreads();        // RAW visibility; also the WAR fence for kt+1's write

        const uint32_t stage = (uint32_t)(kt % NSTAGE) * STAGE_B;

        #pragma unroll
        for (int k16 = 0; k16 < 4; k16++) {
            uint32_t ra[2][4][4];
            uint32_t rb[2][2][4];
            #pragma unroll
            for (int hl = 0; hl < 2; hl++) {
                const uint32_t abase = sb + stage + hl * BUF_B;
                #pragma unroll
                for (int mf = 0; mf < 4; mf++) {
                    const int row = warp_m + mf * 16 + (lane & 15);
                    const int col = ((lane >> 4) << 3) + k16 * 16;
                    ldmx4(ra[hl][mf], abase + row * (LDT * 2) + col * 2);
                }
                const uint32_t bbase = sb + stage + (2 + hl) * BUF_B;
                #pragma unroll
                for (int nf2 = 0; nf2 < 2; nf2++) {
                    const int row = warp_n + nf2 * 16 + ((lane >> 4) << 3) + (lane & 7);
                    const int col = (((lane >> 3) & 1) << 3) + k16 * 16;
                    ldmx4(rb[hl][nf2], bbase + row * (LDT * 2) + col * 2);
                }
            }
            #pragma unroll
            for (int t = 0; t < 3; t++) {
                const int ah = (t == 2) ? 1 : 0;
                const int bh = (t == 1) ? 1 : 0;
                #pragma unroll
                for (int mf = 0; mf < 4; mf++)
                    #pragma unroll
                    for (int nf = 0; nf < 4; nf++)
                        mma_bf16(d[mf][nf], ra[ah][mf], &rb[bh][nf >> 1][(nf & 1) * 2]);
            }
        }
    }

    #pragma unroll
    for (int nf = 0; nf < 4; nf++) {
        const int c0 = bn + warp_n + nf * 8 + (lane & 3) * 2;
        const float b0 = bias[c0], b1 = bias[c0 + 1];
        #pragma unroll
        for (int mf = 0; mf < 4; mf++) {
            const int r0 = bm + warp_m + mf * 16 + (lane >> 2);
            float2 v0, v1;
            v0.x = d[mf][nf][0] + b0; v0.y = d[mf][nf][1] + b1;
            v1.x = d[mf][nf][2] + b0; v1.y = d[mf][nf][3] + b1;
            *(float2*)&C[(size_t)r0 * N + c0]       = v0;
            *(float2*)&C[(size_t)(r0 + 8) * N + c0] = v1;
        }
    }
}

// ---------------------------------------------------------------------------
// Tensor-core windowed causal flash attention (3-term split-bf16).
//   Unchanged from R4 (passing, rel_err 2.5e-5).
// ---------------------------------------------------------------------------
#define SQE 136
#define SQB (SQE * 2)
#define ATILE_B (64 * SQB)      // 17408 B
#define ATTN_SMEM (4 * ATILE_B) // 69632 B

__device__ __forceinline__ void load_conv(char* hi, char* lo, const float* __restrict__ src)
{
    const int tid = threadIdx.x;
    #pragma unroll
    for (int it = 0; it < 16; it++) {
        const int lin = tid + it * 128;
        const int r = lin >> 5;
        const int c = (lin & 31) * 4;
        float4 v = *(const float4*)&src[(size_t)r * QKV_N + c];
        uint32_t h0, l0, h1, l1;
        split2(v.x, v.y, h0, l0);
        split2(v.z, v.w, h1, l1);
        const int byte = r * SQB + c * 2;
        *(uint32_t*)(hi + byte)     = h0;
        *(uint32_t*)(hi + byte + 4) = h1;
        *(uint32_t*)(lo + byte)     = l0;
        *(uint32_t*)(lo + byte + 4) = l1;
    }
}

__global__ __launch_bounds__(128)
void attn_mma_kernel(const float* __restrict__ qkv,
                     __nv_bfloat16* __restrict__ ohi, __nv_bfloat16* __restrict__ olo)
{
    extern __shared__ char asmem[];
    char* QHI = asmem;
    char* QLO = asmem + ATILE_B;
    char* KVH = asmem + 2 * ATILE_B;
    char* KVL = asmem + 3 * ATILE_B;
    const uint32_t sb = smem_u32(asmem);
    const uint32_t KVH_U = sb + 2 * ATILE_B;
    const uint32_t KVL_U = sb + 3 * ATILE_B;

    const int tid = threadIdx.x;
    const int wid = tid >> 5;
    const int lane = tid & 31;
    const int qb = blockIdx.x;
    const int n  = blockIdx.y;
    const int bh = blockIdx.z;
    const int b  = bh >> 4;
    const int h  = bh & 15;

    const size_t row0 = (size_t)b * SEQ + (size_t)n * WINDOW;
    const float* qptr = qkv + (row0 + qb * 64) * QKV_N + h * D_HEAD;
    const float* kbase = qkv + row0 * QKV_N + h * D_HEAD + D_MODEL;
    const float* vbase = qkv + row0 * QKV_N + h * D_HEAD + 2 * D_MODEL;

    load_conv(QHI, QLO, qptr);

    const int warp_m = wid * 16;
    const int r0 = lane >> 2;
    const int qq = lane & 3;

    float o[16][4];
    #pragma unroll
    for (int j = 0; j < 16; j++)
        #pragma unroll
        for (int r = 0; r < 4; r++) o[j][r] = 0.0f;
    float m0 = -1e30f, m1 = -1e30f, l0 = 0.0f, l1 = 0.0f;

    for (int jt = 0; jt <= qb; jt++) {
        __syncthreads();
        load_conv(KVH, KVL, kbase + (size_t)(jt * 64) * QKV_N);
        __syncthreads();

        float s[8][4];
        #pragma unroll
        for (int j = 0; j < 8; j++)
            #pragma unroll
            for (int r = 0; r < 4; r++) s[j][r] = 0.0f;

        #pragma unroll
        for (int k16 = 0; k16 < 8; k16++) {
            uint32_t ra[2][4], rb[2][4][4];
            #pragma unroll
            for (int hl = 0; hl < 2; hl++) {
                const uint32_t ab = sb + (hl ? ATILE_B : 0u);
                ldmx4(ra[hl], ab + (warp_m + (lane & 15)) * SQB
                                 + (((lane >> 4) << 3) + k16 * 16) * 2);
                const uint32_t bb = hl ? KVL_U : KVH_U;
                #pragma unroll
                for (int g = 0; g < 4; g++) {
                    const int row = g * 16 + ((lane >> 4) << 3) + (lane & 7);
                    const int col = (((lane >> 3) & 1) << 3) + k16 * 16;
                    ldmx4(rb[hl][g], bb + row * SQB + col * 2);
                }
            }
            #pragma unroll
            for (int t = 0; t < 3; t++) {
                const int ah = (t == 2) ? 1 : 0;
                const int bl = (t == 1) ? 1 : 0;
                #pragma unroll
                for (int j = 0; j < 8; j++)
                    mma_bf16(s[j], ra[ah], &rb[bl][j >> 1][(j & 1) * 2]);
            }
        }

        const int rg0 = warp_m + r0;
        #pragma unroll
        for (int j = 0; j < 8; j++)
            #pragma unroll
            for (int r = 0; r < 4; r++) s[j][r] *= SCALE_F;
        if (jt == qb) {
            #pragma unroll
            for (int j = 0; j < 8; j++) {
                const int c0 = j * 8 + qq * 2;
                if (c0     > rg0)     s[j][0] = -1e30f;
                if (c0 + 1 > rg0)     s[j][1] = -1e30f;
                if (c0     > rg0 + 8) s[j][2] = -1e30f;
                if (c0 + 1 > rg0 + 8) s[j][3] = -1e30f;
            }
        }

        float mx0 = -1e30f, mx1 = -1e30f;
        #pragma unroll
        for (int j = 0; j < 8; j++) {
            mx0 = fmaxf(mx0, fmaxf(s[j][0], s[j][1]));
            mx1 = fmaxf(mx1, fmaxf(s[j][2], s[j][3]));
        }
        #pragma unroll
        for (int off = 1; off < 4; off <<= 1) {
            mx0 = fmaxf(mx0, __shfl_xor_sync(0xffffffffu, mx0, off));
            mx1 = fmaxf(mx1, __shfl_xor_sync(0xffffffffu, mx1, off));
        }
        const float mn0 = fmaxf(m0, mx0), mn1 = fmaxf(m1, mx1);
        const float f0 = exp2f((m0 - mn0) * LOG2E_F);
        const float f1 = exp2f((m1 - mn1) * LOG2E_F);
        float rs0 = 0.0f, rs1 = 0.0f;
        #pragma unroll
        for (int j = 0; j < 8; j++) {
            s[j][0] = exp2f((s[j][0] - mn0) * LOG2E_F); rs0 += s[j][0];
            s[j][1] = exp2f((s[j][1] - mn0) * LOG2E_F); rs0 += s[j][1];
            s[j][2] = exp2f((s[j][2] - mn1) * LOG2E_F); rs1 += s[j][2];
            s[j][3] = exp2f((s[j][3] - mn1) * LOG2E_F); rs1 += s[j][3];
        }
        #pragma unroll
        for (int off = 1; off < 4; off <<= 1) {
            rs0 += __shfl_xor_sync(0xffffffffu, rs0, off);
            rs1 += __shfl_xor_sync(0xffffffffu, rs1, off);
        }
        l0 = l0 * f0 + rs0; m0 = mn0;
        l1 = l1 * f1 + rs1; m1 = mn1;
        #pragma unroll
        for (int j = 0; j < 16; j++) {
            o[j][0] *= f0; o[j][1] *= f0;
            o[j][2] *= f1; o[j][3] *= f1;
        }

        uint32_t pah[4][4], pal[4][4];
        #pragma unroll
        for (int kc = 0; kc < 4; kc++) {
            split2(s[2 * kc][0],     s[2 * kc][1],     pah[kc][0], pal[kc][0]);
            split2(s[2 * kc][2],     s[2 * kc][3],     pah[kc][1], pal[kc][1]);
            split2(s[2 * kc + 1][0], s[2 * kc + 1][1], pah[kc][2], pal[kc][2]);
            split2(s[2 * kc + 1][2], s[2 * kc + 1][3], pah[kc][3], pal[kc][3]);
        }

        __syncthreads();
        load_conv(KVH, KVL, vbase + (size_t)(jt * 64) * QKV_N);
        __syncthreads();

        const int vrow_part = ((lane >> 3) & 1) * 8 + (lane & 7);
        const int vcol_part = (lane >> 4) * 8;
        #pragma unroll
        for (int kc = 0; kc < 4; kc++) {
            #pragma unroll
            for (int d16 = 0; d16 < 8; d16++) {
                uint32_t vh[4], vl[4];
                const uint32_t off = (kc * 16 + vrow_part) * SQB + (d16 * 16 + vcol_part) * 2;
                ldmx4t(vh, KVH_U + off);
                ldmx4t(vl, KVL_U + off);
                mma_bf16(o[2 * d16],     pah[kc], &vh[0]);
                mma_bf16(o[2 * d16 + 1], pah[kc], &vh[2]);
                mma_bf16(o[2 * d16],     pah[kc], &vl[0]);
                mma_bf16(o[2 * d16 + 1], pah[kc], &vl[2]);
                mma_bf16(o[2 * d16],     pal[kc], &vh[0]);
                mma_bf16(o[2 * d16 + 1], pal[kc], &vh[2]);
            }
        }
    }

    const float inv0 = 1.0f / l0, inv1 = 1.0f / l1;
    const size_t gr0 = row0 + qb * 64 + warp_m + r0;
    const size_t gr1 = gr0 + 8;
    #pragma unroll
    for (int j = 0; j < 16; j++) {
        const int col = h * D_HEAD + j * 8 + qq * 2;
        uint32_t h0, lo0, h1, lo1;
        split2(o[j][0] * inv0, o[j][1] * inv0, h0, lo0);
        split2(o[j][2] * inv1, o[j][3] * inv1, h1, lo1);
        *(uint32_t*)&ohi[gr0 * KDIM + col] = h0;
        *(uint32_t*)&olo[gr0 * KDIM + col] = lo0;
        *(uint32_t*)&ohi[gr1 * KDIM + col] = h1;
        *(uint32_t*)&olo[gr1 * KDIM + col] = lo1;
    }
}

// ---------------------------------------------------------------------------
extern "C" void kernel_launch(void* const* d_in, const int* in_sizes, int n_in,
                              void* d_out, int out_size)
{
    const float* x    = (const float*)d_in[0];
    const float* Wqkv = (const float*)d_in[1];
    const float* bqkv = (const float*)d_in[2];
    const float* Wout = (const float*)d_in[3];
    const float* bout = (const float*)d_in[4];
    float* out = (float*)d_out;

    float* qkv;
    __nv_bfloat16 *ahi, *alo, *wqh, *wql, *woh, *wol;
    cudaGetSymbolAddress((void**)&qkv, g_qkv);
    cudaGetSymbolAddress((void**)&ahi, g_ahi);
    cudaGetSymbolAddress((void**)&alo, g_alo);
    cudaGetSymbolAddress((void**)&wqh, g_wqkv_hi);
    cudaGetSymbolAddress((void**)&wql, g_wqkv_lo);
    cudaGetSymbolAddress((void**)&woh, g_wout_hi);
    cudaGetSymbolAddress((void**)&wol, g_wout_lo);

    cudaFuncSetAttribute(gemm_mma_kernel,
                         cudaFuncAttributeMaxDynamicSharedMemorySize, GEMM_SMEM);
    cudaFuncSetAttribute(attn_mma_kernel,
                         cudaFuncAttributeMaxDynamicSharedMemorySize, ATTN_SMEM);

    transpose_split<<<dim3(QKV_N / 32, KDIM / 32), dim3(32, 8)>>>(Wqkv, wqh, wql, KDIM, QKV_N);
    transpose_split<<<dim3(D_MODEL / 32, KDIM / 32), dim3(32, 8)>>>(Wout, woh, wol, KDIM, D_MODEL);

    {
        const int n4 = ROWS * D_MODEL / 4;
        split_hilo<<<(n4 + 255) / 256, 256>>>(x, ahi, alo, n4);
    }
    gemm_mma_kernel<<<dim3(QKV_N / GBN, ROWS / GBM), 256, GEMM_SMEM>>>(
        ahi, alo, wqh, wql, bqkv, qkv, QKV_N);

    attn_mma_kernel<<<dim3(WINDOW / 64, NB, BATCH * N_HEADS), 128, ATTN_SMEM>>>(qkv, ahi, alo);

    gemm_mma_kernel<<<dim3(D_MODEL / GBN, ROWS / GBM), 256, GEMM_SMEM>>>(
        ahi, alo, woh, wol, bout, out, D_MODEL);
}

// round 7
// speedup vs baseline: 1.2171x; 1.0148x over previous
#include <cuda_runtime.h>
#include <cuda_bf16.h>
#include <cstdint>
#include <cstddef>

// Problem constants
#define D_MODEL 2048
#define N_HEADS 16
#define D_HEAD  128
#define WINDOW  512
#define BATCH   2
#define SEQ     4096
#define NB      (SEQ / WINDOW)
#define ROWS    (BATCH * SEQ)         // 8192
#define QKV_N   (3 * D_MODEL)         // 6144
#define KDIM    D_MODEL               // 2048
#define SCALE_F 0.08838834764831845f
#define LOG2E_F 1.4426950408889634f

// ---------------------------------------------------------------------------
// Scratch (__device__ globals; no allocation allowed)
// ---------------------------------------------------------------------------
__device__ float          g_qkv[(size_t)ROWS * QKV_N];
__device__ __nv_bfloat16  g_ahi[(size_t)ROWS * KDIM];
__device__ __nv_bfloat16  g_alo[(size_t)ROWS * KDIM];
__device__ __nv_bfloat16  g_wqkv_hi[(size_t)QKV_N * KDIM];
__device__ __nv_bfloat16  g_wqkv_lo[(size_t)QKV_N * KDIM];
__device__ __nv_bfloat16  g_wout_hi[(size_t)D_MODEL * KDIM];
__device__ __nv_bfloat16  g_wout_lo[(size_t)D_MODEL * KDIM];

// ---------------------------------------------------------------------------
// Baseline-ISA helpers (NO tcgen05 — ptxas target is compute_103)
// ---------------------------------------------------------------------------
__device__ __forceinline__ uint32_t smem_u32(const void* p) {
    uint32_t a;
    asm("{ .reg .u64 t; cvta.to.shared.u64 t, %1; cvt.u32.u64 %0, t; }" : "=r"(a) : "l"(p));
    return a;
}
#define CP_ASYNC16(dst, src) \
    asm volatile("cp.async.cg.shared.global [%0], [%1], 16;" :: "r"(dst), "l"(src))
#define CP_COMMIT()   asm volatile("cp.async.commit_group;" ::: "memory")
#define CP_WAITG(n)   asm volatile("cp.async.wait_group %0;" :: "n"(n) : "memory")

__device__ __forceinline__ void ldmx4(uint32_t* r, uint32_t addr) {
    asm volatile("ldmatrix.sync.aligned.m8n8.x4.shared.b16 {%0,%1,%2,%3}, [%4];"
                 : "=r"(r[0]), "=r"(r[1]), "=r"(r[2]), "=r"(r[3]) : "r"(addr));
}
__device__ __forceinline__ void ldmx4t(uint32_t* r, uint32_t addr) {
    asm volatile("ldmatrix.sync.aligned.m8n8.x4.trans.shared.b16 {%0,%1,%2,%3}, [%4];"
                 : "=r"(r[0]), "=r"(r[1]), "=r"(r[2]), "=r"(r[3]) : "r"(addr));
}
__device__ __forceinline__ void mma_bf16(float* d, const uint32_t* a, const uint32_t* b) {
    asm volatile("mma.sync.aligned.m16n8k16.row.col.f32.bf16.bf16.f32 "
                 "{%0,%1,%2,%3}, {%4,%5,%6,%7}, {%8,%9}, {%0,%1,%2,%3};"
                 : "+f"(d[0]), "+f"(d[1]), "+f"(d[2]), "+f"(d[3])
                 : "r"(a[0]), "r"(a[1]), "r"(a[2]), "r"(a[3]), "r"(b[0]), "r"(b[1]));
}
__device__ __forceinline__ void split2(float a, float b, uint32_t& h, uint32_t& l) {
    __nv_bfloat16 ha = __float2bfloat16(a), hb = __float2bfloat16(b);
    __nv_bfloat162 hv(ha, hb);
    __nv_bfloat162 lv(__float2bfloat16(a - __bfloat162float(ha)),
                      __float2bfloat16(b - __bfloat162float(hb)));
    h = *(uint32_t*)&hv; l = *(uint32_t*)&lv;
}

// ---------------------------------------------------------------------------
// Conversion kernels
// ---------------------------------------------------------------------------
__global__ void split_hilo(const float* __restrict__ in, __nv_bfloat16* __restrict__ hi,
                           __nv_bfloat16* __restrict__ lo, int n4)
{
    int i = blockIdx.x * blockDim.x + threadIdx.x;
    if (i >= n4) return;
    float4 v = ((const float4*)in)[i];
    uint32_t h0, l0, h1, l1;
    split2(v.x, v.y, h0, l0);
    split2(v.z, v.w, h1, l1);
    ((uint32_t*)hi)[i * 2]     = h0;
    ((uint32_t*)hi)[i * 2 + 1] = h1;
    ((uint32_t*)lo)[i * 2]     = l0;
    ((uint32_t*)lo)[i * 2 + 1] = l1;
}

// W[K,N] fp32 -> Wt hi/lo [N,K] bf16 (transpose + split)
__global__ void transpose_split(const float* __restrict__ W, __nv_bfloat16* __restrict__ hi,
                                __nv_bfloat16* __restrict__ lo, int K, int N)
{
    __shared__ float t[32][33];
    const int n0 = blockIdx.x * 32, k0 = blockIdx.y * 32;
    const int tx = threadIdx.x, ty = threadIdx.y;
    #pragma unroll
    for (int i = 0; i < 4; i++)
        t[ty + i * 8][tx] = W[(size_t)(k0 + ty + i * 8) * N + n0 + tx];
    __syncthreads();
    #pragma unroll
    for (int i = 0; i < 4; i++) {
        float v = t[tx][ty + i * 8];
        size_t o = (size_t)(n0 + ty + i * 8) * K + k0 + tx;
        __nv_bfloat16 h = __float2bfloat16(v);
        hi[o] = h;
        lo[o] = __float2bfloat16(v - __bfloat162float(h));
    }
}

// ---------------------------------------------------------------------------
// mma.sync split-bf16 GEMM.  CTA 128x128, 8 warps (64x32 each), BK=64.
//   3-stage cp.async pipeline, one __syncthreads per k-iteration, and
//   REGISTER DOUBLE-BUFFERED fragments: k16+1's LDSMs issue before k16's MMAs.
// ---------------------------------------------------------------------------
#define GBM 128
#define GBN 128
#define GBK 64
#define LDT 72                        // padded row stride (bf16); 144 B
#define BUF_B (128 * LDT * 2)         // 18432 B
#define STAGE_B (4 * BUF_B)           // 73728 B
#define NSTAGE 3
#define GEMM_SMEM (NSTAGE * STAGE_B)  // 221184 B

__device__ __forceinline__ void load_stage(
    uint32_t sb, uint32_t stage,
    const __nv_bfloat16* __restrict__ ahi, const __nv_bfloat16* __restrict__ alo,
    const __nv_bfloat16* __restrict__ bhi, const __nv_bfloat16* __restrict__ blo,
    int bm, int bn, int k0, int tid)
{
    #pragma unroll
    for (int it = 0; it < 16; it++) {
        const int c = tid + it * 256;
        const int buf = c >> 10;
        const int row = (c >> 3) & 127;
        const int kc = c & 7;
        const __nv_bfloat16* src;
        int grow;
        if (buf == 0)      { src = ahi; grow = bm + row; }
        else if (buf == 1) { src = alo; grow = bm + row; }
        else if (buf == 2) { src = bhi; grow = bn + row; }
        else               { src = blo; grow = bn + row; }
        const uint32_t dst = sb + stage + buf * BUF_B + row * (LDT * 2) + kc * 16;
        CP_ASYNC16(dst, src + (size_t)grow * KDIM + k0 + kc * 8);
    }
}

// load all fragments for one k16 sub-step
__device__ __forceinline__ void ld_frags(
    uint32_t sb, uint32_t stage, int k16, int warp_m, int warp_n, int lane,
    uint32_t ra[2][4][4], uint32_t rb[2][2][4])
{
    #pragma unroll
    for (int hl = 0; hl < 2; hl++) {
        const uint32_t abase = sb + stage + hl * BUF_B;
        #pragma unroll
        for (int mf = 0; mf < 4; mf++) {
            const int row = warp_m + mf * 16 + (lane & 15);
            const int col = ((lane >> 4) << 3) + k16 * 16;
            ldmx4(ra[hl][mf], abase + row * (LDT * 2) + col * 2);
        }
        const uint32_t bbase = sb + stage + (2 + hl) * BUF_B;
        #pragma unroll
        for (int nf2 = 0; nf2 < 2; nf2++) {
            const int row = warp_n + nf2 * 16 + ((lane >> 4) << 3) + (lane & 7);
            const int col = (((lane >> 3) & 1) << 3) + k16 * 16;
            ldmx4(rb[hl][nf2], bbase + row * (LDT * 2) + col * 2);
        }
    }
}

__global__ __launch_bounds__(256, 1)
void gemm_mma_kernel(const __nv_bfloat16* __restrict__ ahi, const __nv_bfloat16* __restrict__ alo,
                     const __nv_bfloat16* __restrict__ bhi, const __nv_bfloat16* __restrict__ blo,
                     const float* __restrict__ bias, float* __restrict__ C, int N)
{
    extern __shared__ char smem[];
    const uint32_t sb = smem_u32(smem);
    const int tid = threadIdx.x;
    const int wid = tid >> 5;
    const int lane = tid & 31;
    const int bm = blockIdx.y * GBM;
    const int bn = blockIdx.x * GBN;
    const int warp_m = (wid >> 2) * 64;
    const int warp_n = (wid & 3) * 32;

    float d[4][4][4];
    #pragma unroll
    for (int i = 0; i < 4; i++)
        #pragma unroll
        for (int j = 0; j < 4; j++)
            #pragma unroll
            for (int r = 0; r < 4; r++) d[i][j][r] = 0.0f;

    const int nk = KDIM / GBK;  // 32

    load_stage(sb, 0, ahi, alo, bhi, blo, bm, bn, 0, tid);
    CP_COMMIT();

    uint32_t ra[2][2][4][4];   // [buf][hi/lo][mf][reg]
    uint32_t rb[2][2][2][4];   // [buf][hi/lo][nf2][reg]

    for (int kt = 0; kt < nk; kt++) {
        if (kt + 1 < nk)
            load_stage(sb, (uint32_t)((kt + 1) % NSTAGE) * STAGE_B,
                       ahi, alo, bhi, blo, bm, bn, (kt + 1) * GBK, tid);
        CP_COMMIT();
        CP_WAITG(1);
        __syncthreads();

        const uint32_t stage = (uint32_t)(kt % NSTAGE) * STAGE_B;

        ld_frags(sb, stage, 0, warp_m, warp_n, lane, ra[0], rb[0]);

        #pragma unroll
        for (int k16 = 0; k16 < 4; k16++) {
            const int cur = k16 & 1;
            if (k16 < 3)
                ld_frags(sb, stage, k16 + 1, warp_m, warp_n, lane,
                         ra[cur ^ 1], rb[cur ^ 1]);
            #pragma unroll
            for (int t = 0; t < 3; t++) {
                const int ah = (t == 2) ? 1 : 0;
                const int bh = (t == 1) ? 1 : 0;
                #pragma unroll
                for (int mf = 0; mf < 4; mf++)
                    #pragma unroll
                    for (int nf = 0; nf < 4; nf++)
                        mma_bf16(d[mf][nf], ra[cur][ah][mf],
                                 &rb[cur][bh][nf >> 1][(nf & 1) * 2]);
            }
        }
    }

    #pragma unroll
    for (int nf = 0; nf < 4; nf++) {
        const int c0 = bn + warp_n + nf * 8 + (lane & 3) * 2;
        const float b0 = bias[c0], b1 = bias[c0 + 1];
        #pragma unroll
        for (int mf = 0; mf < 4; mf++) {
            const int r0 = bm + warp_m + mf * 16 + (lane >> 2);
            float2 v0, v1;
            v0.x = d[mf][nf][0] + b0; v0.y = d[mf][nf][1] + b1;
            v1.x = d[mf][nf][2] + b0; v1.y = d[mf][nf][3] + b1;
            *(float2*)&C[(size_t)r0 * N + c0]       = v0;
            *(float2*)&C[(size_t)(r0 + 8) * N + c0] = v1;
        }
    }
}

// ---------------------------------------------------------------------------
// Tensor-core windowed causal flash attention (3-term split-bf16).
//   Unchanged from R4 (passing, rel_err 2.5e-5).
// ---------------------------------------------------------------------------
#define SQE 136
#define SQB (SQE * 2)
#define ATILE_B (64 * SQB)      // 17408 B
#define ATTN_SMEM (4 * ATILE_B) // 69632 B

__device__ __forceinline__ void load_conv(char* hi, char* lo, const float* __restrict__ src)
{
    const int tid = threadIdx.x;
    #pragma unroll
    for (int it = 0; it < 16; it++) {
        const int lin = tid + it * 128;
        const int r = lin >> 5;
        const int c = (lin & 31) * 4;
        float4 v = *(const float4*)&src[(size_t)r * QKV_N + c];
        uint32_t h0, l0, h1, l1;
        split2(v.x, v.y, h0, l0);
        split2(v.z, v.w, h1, l1);
        const int byte = r * SQB + c * 2;
        *(uint32_t*)(hi + byte)     = h0;
        *(uint32_t*)(hi + byte + 4) = h1;
        *(uint32_t*)(lo + byte)     = l0;
        *(uint32_t*)(lo + byte + 4) = l1;
    }
}

__global__ __launch_bounds__(128)
void attn_mma_kernel(const float* __restrict__ qkv,
                     __nv_bfloat16* __restrict__ ohi, __nv_bfloat16* __restrict__ olo)
{
    extern __shared__ char asmem[];
    char* QHI = asmem;
    char* QLO = asmem + ATILE_B;
    char* KVH = asmem + 2 * ATILE_B;
    char* KVL = asmem + 3 * ATILE_B;
    const uint32_t sb = smem_u32(asmem);
    const uint32_t KVH_U = sb + 2 * ATILE_B;
    const uint32_t KVL_U = sb + 3 * ATILE_B;

    const int tid = threadIdx.x;
    const int wid = tid >> 5;
    const int lane = tid & 31;
    const int qb = blockIdx.x;
    const int n  = blockIdx.y;
    const int bh = blockIdx.z;
    const int b  = bh >> 4;
    const int h  = bh & 15;

    const size_t row0 = (size_t)b * SEQ + (size_t)n * WINDOW;
    const float* qptr = qkv + (row0 + qb * 64) * QKV_N + h * D_HEAD;
    const float* kbase = qkv + row0 * QKV_N + h * D_HEAD + D_MODEL;
    const float* vbase = qkv + row0 * QKV_N + h * D_HEAD + 2 * D_MODEL;

    load_conv(QHI, QLO, qptr);

    const int warp_m = wid * 16;
    const int r0 = lane >> 2;
    const int qq = lane & 3;

    float o[16][4];
    #pragma unroll
    for (int j = 0; j < 16; j++)
        #pragma unroll
        for (int r = 0; r < 4; r++) o[j][r] = 0.0f;
    float m0 = -1e30f, m1 = -1e30f, l0 = 0.0f, l1 = 0.0f;

    for (int jt = 0; jt <= qb; jt++) {
        __syncthreads();
        load_conv(KVH, KVL, kbase + (size_t)(jt * 64) * QKV_N);
        __syncthreads();

        float s[8][4];
        #pragma unroll
        for (int j = 0; j < 8; j++)
            #pragma unroll
            for (int r = 0; r < 4; r++) s[j][r] = 0.0f;

        #pragma unroll
        for (int k16 = 0; k16 < 8; k16++) {
            uint32_t ra[2][4], rb[2][4][4];
            #pragma unroll
            for (int hl = 0; hl < 2; hl++) {
                const uint32_t ab = sb + (hl ? ATILE_B : 0u);
                ldmx4(ra[hl], ab + (warp_m + (lane & 15)) * SQB
                                 + (((lane >> 4) << 3) + k16 * 16) * 2);
                const uint32_t bb = hl ? KVL_U : KVH_U;
                #pragma unroll
                for (int g = 0; g < 4; g++) {
                    const int row = g * 16 + ((lane >> 4) << 3) + (lane & 7);
                    const int col = (((lane >> 3) & 1) << 3) + k16 * 16;
                    ldmx4(rb[hl][g], bb + row * SQB + col * 2);
                }
            }
            #pragma unroll
            for (int t = 0; t < 3; t++) {
                const int ah = (t == 2) ? 1 : 0;
                const int bl = (t == 1) ? 1 : 0;
                #pragma unroll
                for (int j = 0; j < 8; j++)
                    mma_bf16(s[j], ra[ah], &rb[bl][j >> 1][(j & 1) * 2]);
            }
        }

        const int rg0 = warp_m + r0;
        #pragma unroll
        for (int j = 0; j < 8; j++)
            #pragma unroll
            for (int r = 0; r < 4; r++) s[j][r] *= SCALE_F;
        if (jt == qb) {
            #pragma unroll
            for (int j = 0; j < 8; j++) {
                const int c0 = j * 8 + qq * 2;
                if (c0     > rg0)     s[j][0] = -1e30f;
                if (c0 + 1 > rg0)     s[j][1] = -1e30f;
                if (c0     > rg0 + 8) s[j][2] = -1e30f;
                if (c0 + 1 > rg0 + 8) s[j][3] = -1e30f;
            }
        }

        float mx0 = -1e30f, mx1 = -1e30f;
        #pragma unroll
        for (int j = 0; j < 8; j++) {
            mx0 = fmaxf(mx0, fmaxf(s[j][0], s[j][1]));
            mx1 = fmaxf(mx1, fmaxf(s[j][2], s[j][3]));
        }
        #pragma unroll
        for (int off = 1; off < 4; off <<= 1) {
            mx0 = fmaxf(mx0, __shfl_xor_sync(0xffffffffu, mx0, off));
            mx1 = fmaxf(mx1, __shfl_xor_sync(0xffffffffu, mx1, off));
        }
        const float mn0 = fmaxf(m0, mx0), mn1 = fmaxf(m1, mx1);
        const float f0 = exp2f((m0 - mn0) * LOG2E_F);
        const float f1 = exp2f((m1 - mn1) * LOG2E_F);
        float rs0 = 0.0f, rs1 = 0.0f;
        #pragma unroll
        for (int j = 0; j < 8; j++) {
            s[j][0] = exp2f((s[j][0] - mn0) * LOG2E_F); rs0 += s[j][0];
            s[j][1] = exp2f((s[j][1] - mn0) * LOG2E_F); rs0 += s[j][1];
            s[j][2] = exp2f((s[j][2] - mn1) * LOG2E_F); rs1 += s[j][2];
            s[j][3] = exp2f((s[j][3] - mn1) * LOG2E_F); rs1 += s[j][3];
        }
        #pragma unroll
        for (int off = 1; off < 4; off <<= 1) {
            rs0 += __shfl_xor_sync(0xffffffffu, rs0, off);
            rs1 += __shfl_xor_sync(0xffffffffu, rs1, off);
        }
        l0 = l0 * f0 + rs0; m0 = mn0;
        l1 = l1 * f1 + rs1; m1 = mn1;
        #pragma unroll
        for (int j = 0; j < 16; j++) {
            o[j][0] *= f0; o[j][1] *= f0;
            o[j][2] *= f1; o[j][3] *= f1;
        }

        uint32_t pah[4][4], pal[4][4];
        #pragma unroll
        for (int kc = 0; kc < 4; kc++) {
            split2(s[2 * kc][0],     s[2 * kc][1],     pah[kc][0], pal[kc][0]);
            split2(s[2 * kc][2],     s[2 * kc][3],     pah[kc][1], pal[kc][1]);
            split2(s[2 * kc + 1][0], s[2 * kc + 1][1], pah[kc][2], pal[kc][2]);
            split2(s[2 * kc + 1][2], s[2 * kc + 1][3], pah[kc][3], pal[kc][3]);
        }

        __syncthreads();
        load_conv(KVH, KVL, vbase + (size_t)(jt * 64) * QKV_N);
        __syncthreads();

        const int vrow_part = ((lane >> 3) & 1) * 8 + (lane & 7);
        const int vcol_part = (lane >> 4) * 8;
        #pragma unroll
        for (int kc = 0; kc < 4; kc++) {
            #pragma unroll
            for (int d16 = 0; d16 < 8; d16++) {
                uint32_t vh[4], vl[4];
                const uint32_t off = (kc * 16 + vrow_part) * SQB + (d16 * 16 + vcol_part) * 2;
                ldmx4t(vh, KVH_U + off);
                ldmx4t(vl, KVL_U + off);
                mma_bf16(o[2 * d16],     pah[kc], &vh[0]);
                mma_bf16(o[2 * d16 + 1], pah[kc], &vh[2]);
                mma_bf16(o[2 * d16],     pah[kc], &vl[0]);
                mma_bf16(o[2 * d16 + 1], pah[kc], &vl[2]);
                mma_bf16(o[2 * d16],     pal[kc], &vh[0]);
                mma_bf16(o[2 * d16 + 1], pal[kc], &vh[2]);
            }
        }
    }

    const float inv0 = 1.0f / l0, inv1 = 1.0f / l1;
    const size_t gr0 = row0 + qb * 64 + warp_m + r0;
    const size_t gr1 = gr0 + 8;
    #pragma unroll
    for (int j = 0; j < 16; j++) {
        const int col = h * D_HEAD + j * 8 + qq * 2;
        uint32_t h0, lo0, h1, lo1;
        split2(o[j][0] * inv0, o[j][1] * inv0, h0, lo0);
        split2(o[j][2] * inv1, o[j][3] * inv1, h1, lo1);
        *(uint32_t*)&ohi[gr0 * KDIM + col] = h0;
        *(uint32_t*)&olo[gr0 * KDIM + col] = lo0;
        *(uint32_t*)&ohi[gr1 * KDIM + col] = h1;
        *(uint32_t*)&olo[gr1 * KDIM + col] = lo1;
    }
}

// ---------------------------------------------------------------------------
extern "C" void kernel_launch(void* const* d_in, const int* in_sizes, int n_in,
                              void* d_out, int out_size)
{
    const float* x    = (const float*)d_in[0];
    const float* Wqkv = (const float*)d_in[1];
    const float* bqkv = (const float*)d_in[2];
    const float* Wout = (const float*)d_in[3];
    const float* bout = (const float*)d_in[4];
    float* out = (float*)d_out;

    float* qkv;
    __nv_bfloat16 *ahi, *alo, *wqh, *wql, *woh, *wol;
    cudaGetSymbolAddress((void**)&qkv, g_qkv);
    cudaGetSymbolAddress((void**)&ahi, g_ahi);
    cudaGetSymbolAddress((void**)&alo, g_alo);
    cudaGetSymbolAddress((void**)&wqh, g_wqkv_hi);
    cudaGetSymbolAddress((void**)&wql, g_wqkv_lo);
    cudaGetSymbolAddress((void**)&woh, g_wout_hi);
    cudaGetSymbolAddress((void**)&wol, g_wout_lo);

    cudaFuncSetAttribute(gemm_mma_kernel,
                         cudaFuncAttributeMaxDynamicSharedMemorySize, GEMM_SMEM);
    cudaFuncSetAttribute(attn_mma_kernel,
                         cudaFuncAttributeMaxDynamicSharedMemorySize, ATTN_SMEM);

    transpose_split<<<dim3(QKV_N / 32, KDIM / 32), dim3(32, 8)>>>(Wqkv, wqh, wql, KDIM, QKV_N);
    transpose_split<<<dim3(D_MODEL / 32, KDIM / 32), dim3(32, 8)>>>(Wout, woh, wol, KDIM, D_MODEL);

    {
        const int n4 = ROWS * D_MODEL / 4;
        split_hilo<<<(n4 + 255) / 256, 256>>>(x, ahi, alo, n4);
    }
    gemm_mma_kernel<<<dim3(QKV_N / GBN, ROWS / GBM), 256, GEMM_SMEM>>>(
        ahi, alo, wqh, wql, bqkv, qkv, QKV_N);

    attn_mma_kernel<<<dim3(WINDOW / 64, NB, BATCH * N_HEADS), 128, ATTN_SMEM>>>(qkv, ahi, alo);

    gemm_mma_kernel<<<dim3(D_MODEL / GBN, ROWS / GBM), 256, GEMM_SMEM>>>(
        ahi, alo, woh, wol, bout, out, D_MODEL);
}